// round 1
// baseline (speedup 1.0000x reference)
#include <cuda_runtime.h>

#define N197   197
#define NN     38809        // 197*197
#define NBATCH 32
#define NLAY   2            // processed layers: 4 and 11
#define KDISC  9702         // int(197*197*0.25)

// scratch: head-averaged (then discarded, then normalized in-place) attn for the 2 layers
__device__ float    g_attn[NLAY * NBATCH * NN];   // ~9.93 MB
__device__ unsigned g_key [NLAY * NBATCH];        // bit pattern of k-th smallest
__device__ int      g_need[NLAY * NBATCH];        // # of ==T elements to zero (by index order)

// ---------------------------------------------------------------------------
// 1) mean over heads for layers 4 and 11
// ---------------------------------------------------------------------------
__global__ void mean_kernel(const float* __restrict__ in) {
    const long total = (long)NLAY * NBATCH * NN;
    for (long idx = blockIdx.x * (long)blockDim.x + threadIdx.x; idx < total;
         idx += (long)gridDim.x * blockDim.x) {
        int li  = (int)(idx / ((long)NBATCH * NN));
        int rem = (int)(idx - (long)li * NBATCH * NN);
        int b   = rem / NN;
        int p   = rem - b * NN;
        int layer = li ? 11 : 4;
        const float* base = in + ((long)(layer * NBATCH + b) * 12) * NN + p;
        float s = 0.f;
#pragma unroll
        for (int h = 0; h < 12; h++) s += base[(long)h * NN];
        g_attn[idx] = s * (1.0f / 12.0f);
    }
}

// ---------------------------------------------------------------------------
// 2) exact k-th smallest per (layer,batch) via 3-round radix select on float bits
//    (all values are >= 0, so uint bit order == float order)
// ---------------------------------------------------------------------------
__global__ void select_kernel() {
    int lb = blockIdx.x;
    const float* v = g_attn + (long)lb * NN;

    __shared__ unsigned hist[2048];
    __shared__ unsigned s_prefix, s_rank, s_less;
    if (threadIdx.x == 0) { s_prefix = 0; s_rank = KDISC - 1; s_less = 0; }

    const int shifts[3]  = {21, 10, 0};
    const int widths[3]  = {11, 11, 10};   // 11+11+10 = 32 bits

    for (int r = 0; r < 3; r++) {
        int shift = shifts[r];
        int nb    = 1 << widths[r];
        for (int i = threadIdx.x; i < nb; i += blockDim.x) hist[i] = 0;
        __syncthreads();

        unsigned pf = s_prefix;
        for (int i = threadIdx.x; i < NN; i += blockDim.x) {
            unsigned key = __float_as_uint(v[i]);
            if (r == 0 || (key >> (shift + widths[r])) == pf)
                atomicAdd(&hist[(key >> shift) & (nb - 1)], 1u);
        }
        __syncthreads();

        if (threadIdx.x == 0) {
            unsigned rank = s_rank, cum = 0;
            int chosen = 0;
            for (int bkt = 0; bkt < nb; bkt++) {
                unsigned c = hist[bkt];
                if (cum + c > rank) { chosen = bkt; break; }
                cum += c;
            }
            s_rank   = rank - cum;
            s_less  += cum;
            s_prefix = (pf << widths[r]) | (unsigned)chosen;
        }
        __syncthreads();
    }
    if (threadIdx.x == 0) {
        g_key [lb] = s_prefix;                 // full 32-bit key of the k-th smallest
        g_need[lb] = KDISC - (int)s_less;      // #(==T) to zero, lowest indices first
    }
}

// ---------------------------------------------------------------------------
// 3) zero the k smallest (ties: lowest index first), restore flat index 0.
//    Contiguous per-thread segments + block prefix give exact index ordering.
// ---------------------------------------------------------------------------
__global__ void discard_kernel() {
    int lb = blockIdx.x;
    float* v = g_attn + (long)lb * NN;
    unsigned T = g_key[lb];
    int need   = g_need[lb];

    const int SEG = (NN + 255) / 256;   // 152
    int start = threadIdx.x * SEG;
    int end   = min(start + SEG, NN);

    int cnt = 0;
    for (int i = start; i < end; i++)
        if (__float_as_uint(v[i]) == T) cnt++;

    __shared__ int counts[256];
    __shared__ int pref[256];
    counts[threadIdx.x] = cnt;
    __syncthreads();
    if (threadIdx.x == 0) {
        int s = 0;
        for (int i = 0; i < 256; i++) { pref[i] = s; s += counts[i]; }
    }
    __syncthreads();

    int rank = pref[threadIdx.x];
    for (int i = start; i < end; i++) {
        unsigned key = __float_as_uint(v[i]);
        bool z = false;
        if (key < T) z = true;
        else if (key == T) { if (rank < need) z = true; rank++; }
        if (z && i != 0) v[i] = 0.f;    // i==0: flat[:,0] is restored by the reference
    }
}

// ---------------------------------------------------------------------------
// 4) A[i,j] = (attn[i,j] + d_ij) / (sum_j attn[i,j] + 1)   (the *0.5 cancels)
// ---------------------------------------------------------------------------
__global__ void norm_kernel() {
    int row = blockIdx.x;                 // lb*197 + i
    int lb  = row / N197;
    int i   = row - lb * N197;
    float* v = g_attn + (long)lb * NN + i * N197;

    int t = threadIdx.x;
    float x = (t < N197) ? v[t] : 0.f;

    float s = x;
#pragma unroll
    for (int o = 16; o; o >>= 1) s += __shfl_xor_sync(0xffffffffu, s, o);
    __shared__ float ws[8];
    if ((t & 31) == 0) ws[t >> 5] = s;
    __syncthreads();
    if (t < 8) {
        float y = ws[t];
#pragma unroll
        for (int o = 4; o; o >>= 1) y += __shfl_xor_sync(0xffu, y, o);
        if (t == 0) ws[0] = y;
    }
    __syncthreads();
    float tot = ws[0] + 1.0f;
    if (t < N197) v[t] = (x + ((t == i) ? 1.f : 0.f)) / tot;
}

// ---------------------------------------------------------------------------
// 5) out[b] = A11[b] @ A4[b]   (197x197x197, 32 batches)
//    64x64 tile, BK=16, 256 threads, 4x4 microtile, bounds-checked.
// ---------------------------------------------------------------------------
#define BM 64
#define BN 64
#define BK 16
__global__ void gemm_kernel(float* __restrict__ C) {
    const float* A = g_attn + (long)NBATCH * NN + (long)blockIdx.z * NN; // A11[b]
    const float* B = g_attn + (long)blockIdx.z * NN;                     // A4[b]
    C += (long)blockIdx.z * NN;

    __shared__ float As[BK][BM];
    __shared__ float Bs[BK][BN];

    int tid = threadIdx.x;            // 0..255
    int tx = tid & 15, ty = tid >> 4; // 16x16 thread grid
    int row0 = blockIdx.y * BM, col0 = blockIdx.x * BN;

    float acc[4][4] = {};

    for (int k0 = 0; k0 < N197; k0 += BK) {
#pragma unroll
        for (int l = 0; l < 4; l++) {               // As: 64x16 (stored transposed)
            int idx = tid + l * 256;
            int r = idx >> 4, c = idx & 15;
            int gr = row0 + r, gc = k0 + c;
            As[c][r] = (gr < N197 && gc < N197) ? A[gr * N197 + gc] : 0.f;
        }
#pragma unroll
        for (int l = 0; l < 4; l++) {               // Bs: 16x64
            int idx = tid + l * 256;
            int kr = idx >> 6, cn = idx & 63;
            int gk = k0 + kr, gc = col0 + cn;
            Bs[kr][cn] = (gk < N197 && gc < N197) ? B[gk * N197 + gc] : 0.f;
        }
        __syncthreads();
#pragma unroll
        for (int kk = 0; kk < BK; kk++) {
            float4 a  = *(const float4*)&As[kk][ty * 4];
            float4 bv = *(const float4*)&Bs[kk][tx * 4];
            float av[4] = {a.x, a.y, a.z, a.w};
            float bb[4] = {bv.x, bv.y, bv.z, bv.w};
#pragma unroll
            for (int m = 0; m < 4; m++)
#pragma unroll
                for (int n = 0; n < 4; n++) acc[m][n] += av[m] * bb[n];
        }
        __syncthreads();
    }

#pragma unroll
    for (int m = 0; m < 4; m++) {
        int gr = row0 + ty * 4 + m;
        if (gr >= N197) continue;
#pragma unroll
        for (int n = 0; n < 4; n++) {
            int gc = col0 + tx * 4 + n;
            if (gc < N197) C[gr * N197 + gc] = acc[m][n];
        }
    }
}

// ---------------------------------------------------------------------------
extern "C" void kernel_launch(void* const* d_in, const int* in_sizes, int n_in,
                              void* d_out, int out_size) {
    const float* attn = (const float*)d_in[0];  // (12,32,12,197,197) fp32
    float* out = (float*)d_out;                 // (32,197,197) fp32
    (void)in_sizes; (void)n_in; (void)out_size;

    long total = (long)NLAY * NBATCH * NN;
    int blocks = (int)((total + 255) / 256);
    mean_kernel<<<blocks, 256>>>(attn);
    select_kernel<<<NLAY * NBATCH, 256>>>();
    discard_kernel<<<NLAY * NBATCH, 256>>>();
    norm_kernel<<<NLAY * NBATCH * N197, 256>>>();
    dim3 g((N197 + BN - 1) / BN, (N197 + BM - 1) / BM, NBATCH);
    gemm_kernel<<<g, 256>>>(out);
}

// round 2
// speedup vs baseline: 1.1573x; 1.1573x over previous
#include <cuda_runtime.h>

#define N197   197
#define NN     38809        // 197*197
#define NBATCH 32
#define NLAY   2            // processed layers: 4 and 11
#define KDISC  9702         // int(197*197*0.25)
#define PADR   256          // padded rows for gemm-safe reads
#define PADC   208          // padded cols (13*16, 16B-aligned row stride)

__device__ float g_attn[NLAY * NBATCH * NN];           // head-averaged, then discarded, ~9.9 MB
__device__ float g_norm[NLAY * NBATCH * PADR * PADC];  // normalized, zero-padded, ~13.6 MB

// ---------------------------------------------------------------------------
// 1) mean over heads for layers 4 and 11 (DRAM-bound: 119 MB read)
// ---------------------------------------------------------------------------
__global__ void mean_kernel(const float* __restrict__ in) {
    int lb = blockIdx.y;                 // 0..63 = li*32 + b
    int li = lb >> 5, b = lb & 31;
    int layer = li ? 11 : 4;
    const float* base = in + ((long)(layer * NBATCH + b) * 12) * NN;
    float* dst = g_attn + (long)lb * NN;
    for (int p = blockIdx.x * blockDim.x + threadIdx.x; p < NN;
         p += gridDim.x * blockDim.x) {
        float s = 0.f;
#pragma unroll
        for (int h = 0; h < 12; h++) s += base[(long)h * NN + p];
        dst[p] = s * (1.0f / 12.0f);
    }
}

// ---------------------------------------------------------------------------
// 2) fused: radix-select k-th smallest + discard + row-sum + normalize
//    one block per (layer,batch) matrix; data L2-resident across passes
// ---------------------------------------------------------------------------
#define NT 512
__global__ void __launch_bounds__(NT) fused_kernel() {
    const int lb = blockIdx.x;
    float* v = g_attn + (long)lb * NN;

    __shared__ unsigned hist[2048];
    __shared__ unsigned wtot[16];
    __shared__ float    rowden[N197];      // row sum + 1
    __shared__ int      tie_list[4096];
    __shared__ unsigned s_prefix;
    __shared__ int s_rank, s_less, s_total, s_cnt;

    const int t    = threadIdx.x;
    const int lane = t & 31;
    const int wid  = t >> 5;
    const int ITER = (NN + NT - 1) / NT;   // 76

    if (t == 0) { s_prefix = 0; s_rank = KDISC - 1; s_less = 0; s_total = 0; s_cnt = 0; }
    __syncthreads();

    // ---- 3-round radix select on float bits (all values >= 0) ----
    const int shifts[3] = {21, 10, 0};
    const int widths[3] = {11, 11, 10};
#pragma unroll 1
    for (int r = 0; r < 3; r++) {
        const int shift = shifts[r];
        const int width = widths[r];
        const int nb    = 1 << width;
        for (int i = t; i < nb; i += NT) hist[i] = 0;
        __syncthreads();
        unsigned pf = s_prefix;

        for (int k = 0; k < ITER; k++) {
            int i = k * NT + t;
            bool valid = i < NN;
            unsigned key = valid ? __float_as_uint(v[i]) : 0u;
            bool ok = valid && (r == 0 || (key >> (shift + width)) == pf);
            unsigned mask = __ballot_sync(0xffffffffu, ok);
            if (ok) {
                unsigned bkt = (key >> shift) & (nb - 1);
                unsigned grp = __match_any_sync(mask, bkt);
                if (lane == __ffs(grp) - 1) atomicAdd(&hist[bkt], __popc(grp));
            }
        }
        __syncthreads();

        // parallel scan: each thread owns `per` consecutive buckets
        const int per = nb / NT;           // 4, 4, 2
        unsigned sum = 0;
#pragma unroll 4
        for (int j = 0; j < per; j++) sum += hist[t * per + j];
        unsigned x = sum;                  // inclusive warp scan
#pragma unroll
        for (int o = 1; o < 32; o <<= 1) {
            unsigned y = __shfl_up_sync(0xffffffffu, x, o);
            if (lane >= o) x += y;
        }
        if (lane == 31) wtot[wid] = x;
        __syncthreads();
        if (t < 16) {
            unsigned y = wtot[t];
#pragma unroll
            for (int o = 1; o < 16; o <<= 1) {
                unsigned z = __shfl_up_sync(0xffffu, y, o);
                if (t >= o) y += z;
            }
            wtot[t] = y;
        }
        __syncthreads();
        unsigned incl = x + (wid ? wtot[wid - 1] : 0u);
        unsigned excl = incl - sum;
        unsigned rank = (unsigned)s_rank;
        __syncthreads();
        if (rank >= excl && rank < excl + sum) {   // exactly one thread
            unsigned c = excl;
            int chosen = 0;
            for (int j = 0; j < per; j++) {
                unsigned h = hist[t * per + j];
                if (c + h > rank) { chosen = t * per + j; break; }
                c += h;
            }
            s_rank   = (int)(rank - c);
            s_less  += (int)c;
            s_prefix = (pf << width) | (unsigned)chosen;
        }
        __syncthreads();
    }

    const unsigned T = s_prefix;               // bit pattern of k-th smallest
    const int less   = s_less;
    const int need   = KDISC - less;           // #(==T) to zero, lowest index first

    // ---- count ties ----
    int myt = 0;
    for (int k = 0; k < ITER; k++) {
        int i = k * NT + t;
        if (i < NN && __float_as_uint(v[i]) == T) myt++;
    }
#pragma unroll
    for (int o = 16; o; o >>= 1) myt += __shfl_xor_sync(0xffffffffu, myt, o);
    if (lane == 0 && myt) atomicAdd(&s_total, myt);
    __syncthreads();
    const int total_ties = s_total;

    if (need == total_ties) {
        // fast path: zero everything with key <= T (except flat index 0)
        for (int k = 0; k < ITER; k++) {
            int i = k * NT + t;
            if (i < NN && i != 0 && __float_as_uint(v[i]) <= T) v[i] = 0.f;
        }
    } else {
        // rare path: zero key < T; rank ties by index explicitly
        for (int k = 0; k < ITER; k++) {
            int i = k * NT + t;
            if (i < NN && i != 0 && __float_as_uint(v[i]) < T) v[i] = 0.f;
        }
        if (total_ties <= 4096) {
            for (int k = 0; k < ITER; k++) {
                int i = k * NT + t;
                if (i < NN && __float_as_uint(v[i]) == T)
                    tie_list[atomicAdd(&s_cnt, 1)] = i;
            }
            __syncthreads();
            int cnt = s_cnt;
            for (int e = t; e < cnt; e += NT) {
                int idx = tie_list[e];
                int rk = 0;
                for (int j = 0; j < cnt; j++) rk += (tie_list[j] < idx);
                if (rk < need && idx != 0) v[idx] = 0.f;
            }
        } else if (t == 0) {
            // pathological fallback: serial exact scan
            int rk = 0;
            for (int i = 0; i < NN; i++) {
                if (__float_as_uint(v[i]) == T) {
                    if (rk < need && i != 0) v[i] = 0.f;
                    rk++;
                }
            }
        }
    }
    __syncthreads();

    // ---- row sums: warp per row ----
    for (int r = wid; r < N197; r += 16) {
        const float* row = v + r * N197;
        float s = 0.f;
#pragma unroll
        for (int c = lane; c < N197; c += 32) s += row[c];
#pragma unroll
        for (int o = 16; o; o >>= 1) s += __shfl_xor_sync(0xffffffffu, s, o);
        if (lane == 0) rowden[r] = s + 1.0f;   // the *0.5 cancels: (x+d)/(sum+1)
    }
    __syncthreads();

    // ---- normalized write into zero-padded 256x208 buffer ----
    float* o = g_norm + (long)lb * (PADR * PADC);
    for (int i = t; i < PADR * PADC; i += NT) {
        int r = i / PADC, c = i - r * PADC;
        float val = 0.f;
        if (r < N197 && c < N197)
            val = (v[r * N197 + c] + (r == c ? 1.f : 0.f)) / rowden[r];
        o[i] = val;
    }
}

// ---------------------------------------------------------------------------
// 3) out[b] = A11[b] @ A4[b]; padded inputs -> guard-free mainloop
// ---------------------------------------------------------------------------
#define BM 64
#define BN 64
#define BK 16
__global__ void __launch_bounds__(256) gemm_kernel(float* __restrict__ C) {
    const int b = blockIdx.z;
    const float* A = g_norm + (long)(NBATCH + b) * (PADR * PADC);  // layer 11
    const float* B = g_norm + (long)b * (PADR * PADC);             // layer 4
    C += (long)b * NN;

    __shared__ float As[BK][BM];
    __shared__ float Bs[BK][BN + 4];

    const int tid = threadIdx.x;
    const int tx = tid & 15, ty = tid >> 4;
    const int row0 = blockIdx.y * BM, col0 = blockIdx.x * BN;

    float acc[4][4] = {};

    for (int k0 = 0; k0 < PADC; k0 += BK) {
        {   // As: 64 rows x 16 k, transposed; one float4 per thread
            int r = tid >> 2, cq = tid & 3;
            float4 a = *(const float4*)&A[(row0 + r) * PADC + k0 + cq * 4];
            As[cq * 4 + 0][r] = a.x;
            As[cq * 4 + 1][r] = a.y;
            As[cq * 4 + 2][r] = a.z;
            As[cq * 4 + 3][r] = a.w;
        }
        {   // Bs: 16 k x 64 cols; one float4 per thread
            int kr = tid >> 4, cq = tid & 15;
            float4 bv = *(const float4*)&B[(k0 + kr) * PADC + col0 + cq * 4];
            *(float4*)&Bs[kr][cq * 4] = bv;
        }
        __syncthreads();
#pragma unroll
        for (int kk = 0; kk < BK; kk++) {
            float av[4], bb[4];
#pragma unroll
            for (int m = 0; m < 4; m++) av[m] = As[kk][ty * 4 + m];
#pragma unroll
            for (int n = 0; n < 4; n++) bb[n] = Bs[kk][tx * 4 + n];
#pragma unroll
            for (int m = 0; m < 4; m++)
#pragma unroll
                for (int n = 0; n < 4; n++) acc[m][n] += av[m] * bb[n];
        }
        __syncthreads();
    }

#pragma unroll
    for (int m = 0; m < 4; m++) {
        int gr = row0 + ty * 4 + m;
        if (gr >= N197) continue;
#pragma unroll
        for (int n = 0; n < 4; n++) {
            int gc = col0 + tx * 4 + n;
            if (gc < N197) C[gr * N197 + gc] = acc[m][n];
        }
    }
}

// ---------------------------------------------------------------------------
extern "C" void kernel_launch(void* const* d_in, const int* in_sizes, int n_in,
                              void* d_out, int out_size) {
    const float* attn = (const float*)d_in[0];  // (12,32,12,197,197) fp32
    float* out = (float*)d_out;                 // (32,197,197) fp32
    (void)in_sizes; (void)n_in; (void)out_size;

    dim3 gm(40, NLAY * NBATCH);
    mean_kernel<<<gm, 256>>>(attn);
    fused_kernel<<<NLAY * NBATCH, NT>>>();
    dim3 gg((N197 + BN - 1) / BN, (N197 + BM - 1) / BM, NBATCH);
    gemm_kernel<<<gg, 256>>>(out);
}

// round 3
// speedup vs baseline: 1.7256x; 1.4911x over previous
#include <cuda_runtime.h>

#define N197   197
#define NN     38809        // 197*197
#define NNP    38812        // padded stride (float4-aligned)
#define NBATCH 32
#define NLAY   2            // processed layers: 4 and 11
#define KDISC  9702         // int(197*197*0.25)
#define PADR   256          // padded rows for gemm-safe reads
#define PADC   208          // padded cols (52 float4 per row)

__device__ float g_attn[NLAY * NBATCH * NNP];          // head-averaged, ~9.94 MB
__device__ float g_norm[NLAY * NBATCH * PADR * PADC];  // normalized, zero-padded, ~13.6 MB

// ---------------------------------------------------------------------------
// 1) mean over heads for layers 4 and 11 (DRAM-bound: 119 MB read)
// ---------------------------------------------------------------------------
__global__ void __launch_bounds__(256) mean_kernel(const float* __restrict__ in) {
    int lb = blockIdx.y;                 // 0..63 = li*32 + b
    int li = lb >> 5, b = lb & 31;
    int layer = li ? 11 : 4;
    const float* __restrict__ base = in + ((long)(layer * NBATCH + b) * 12) * NN;
    float* dst = g_attn + (long)lb * NNP;
    int stride = gridDim.x * blockDim.x;
    for (int p = blockIdx.x * blockDim.x + threadIdx.x; p < NN; p += 2 * stride) {
        int p2 = p + stride;
        float s0 = 0.f, s1 = 0.f;
#pragma unroll
        for (int h = 0; h < 12; h++) {
            s0 += __ldg(&base[(long)h * NN + p]);
            if (p2 < NN) s1 += __ldg(&base[(long)h * NN + p2]);
        }
        dst[p] = s0 * (1.0f / 12.0f);
        if (p2 < NN) dst[p2] = s1 * (1.0f / 12.0f);
    }
}

// ---------------------------------------------------------------------------
// 2) fused: whole matrix in SMEM; radix-select + discard + row-sum + normalize
// ---------------------------------------------------------------------------
#define NT 512
__global__ void __launch_bounds__(NT) fused_kernel() {
    extern __shared__ float sm[];          // NN floats (155,236 B dynamic)
    __shared__ unsigned hist[2048];
    __shared__ unsigned wtot[16];
    __shared__ float    rowden[N197];
    __shared__ int      tie_list[4096];
    __shared__ unsigned s_prefix;
    __shared__ int s_rank, s_less, s_total, s_cnt;

    const int lb   = blockIdx.x;
    const int t    = threadIdx.x;
    const int lane = t & 31;
    const int wid  = t >> 5;
    const int ITER = (NN + NT - 1) / NT;   // 76

    // ---- load matrix into smem (float4) ----
    const float* src = g_attn + (long)lb * NNP;
    {
        const float4* s4 = (const float4*)src;
        float4* d4 = (float4*)sm;
        for (int i = t; i < NN / 4; i += NT) d4[i] = s4[i];   // 9702 float4
        if (t == 0) sm[NN - 1] = src[NN - 1];
    }
    if (t == 0) { s_prefix = 0; s_rank = KDISC - 1; s_less = 0; s_total = 0; s_cnt = 0; }
    __syncthreads();

    // ---- 3-round radix select on float bits (all values >= 0) ----
    const int shifts[3] = {21, 10, 0};
    const int widths[3] = {11, 11, 10};
#pragma unroll 1
    for (int r = 0; r < 3; r++) {
        const int shift = shifts[r];
        const int width = widths[r];
        const int nb    = 1 << width;
        for (int i = t; i < nb; i += NT) hist[i] = 0;
        __syncthreads();
        unsigned pf = s_prefix;

        for (int k = 0; k < ITER; k++) {
            int i = k * NT + t;
            bool valid = i < NN;
            unsigned key = valid ? __float_as_uint(sm[i]) : 0u;
            bool ok = valid && (r == 0 || (key >> (shift + width)) == pf);
            unsigned mask = __ballot_sync(0xffffffffu, ok);
            if (ok) {
                unsigned bkt = (key >> shift) & (nb - 1);
                unsigned grp = __match_any_sync(mask, bkt);
                if (lane == __ffs(grp) - 1) atomicAdd(&hist[bkt], __popc(grp));
            }
        }
        __syncthreads();

        // parallel scan: each thread owns `per` consecutive buckets
        const int per = nb / NT;           // 4, 4, 2
        unsigned sum = 0;
#pragma unroll 4
        for (int j = 0; j < per; j++) sum += hist[t * per + j];
        unsigned x = sum;                  // inclusive warp scan
#pragma unroll
        for (int o = 1; o < 32; o <<= 1) {
            unsigned y = __shfl_up_sync(0xffffffffu, x, o);
            if (lane >= o) x += y;
        }
        if (lane == 31) wtot[wid] = x;
        __syncthreads();
        if (t < 16) {
            unsigned y = wtot[t];
#pragma unroll
            for (int o = 1; o < 16; o <<= 1) {
                unsigned z = __shfl_up_sync(0xffffu, y, o);
                if (t >= o) y += z;
            }
            wtot[t] = y;
        }
        __syncthreads();
        unsigned incl = x + (wid ? wtot[wid - 1] : 0u);
        unsigned excl = incl - sum;
        unsigned rank = (unsigned)s_rank;
        __syncthreads();
        if (rank >= excl && rank < excl + sum) {   // exactly one thread enters
            unsigned c = excl;
            int chosen = 0;
            for (int j = 0; j < per; j++) {
                unsigned h = hist[t * per + j];
                if (c + h > rank) { chosen = t * per + j; break; }
                c += h;
            }
            s_rank   = (int)(rank - c);
            s_less  += (int)c;
            s_prefix = (pf << width) | (unsigned)chosen;
        }
        __syncthreads();
    }

    const unsigned T = s_prefix;               // bit pattern of k-th smallest
    const int need   = KDISC - s_less;         // #(==T) to zero, lowest index first

    // ---- count ties ----
    int myt = 0;
    for (int k = 0; k < ITER; k++) {
        int i = k * NT + t;
        if (i < NN && __float_as_uint(sm[i]) == T) myt++;
    }
#pragma unroll
    for (int o = 16; o; o >>= 1) myt += __shfl_xor_sync(0xffffffffu, myt, o);
    if (lane == 0 && myt) atomicAdd(&s_total, myt);
    __syncthreads();
    const int total_ties = s_total;

    if (need == total_ties) {
        // fast path: zero everything with key <= T (except flat index 0)
        for (int k = 0; k < ITER; k++) {
            int i = k * NT + t;
            if (i < NN && i != 0 && __float_as_uint(sm[i]) <= T) sm[i] = 0.f;
        }
    } else {
        for (int k = 0; k < ITER; k++) {
            int i = k * NT + t;
            if (i < NN && i != 0 && __float_as_uint(sm[i]) < T) sm[i] = 0.f;
        }
        if (total_ties <= 4096) {
            for (int k = 0; k < ITER; k++) {
                int i = k * NT + t;
                if (i < NN && __float_as_uint(sm[i]) == T)
                    tie_list[atomicAdd(&s_cnt, 1)] = i;
            }
            __syncthreads();
            int cnt = s_cnt;
            for (int e = t; e < cnt; e += NT) {
                int idx = tie_list[e];
                int rk = 0;
                for (int j = 0; j < cnt; j++) rk += (tie_list[j] < idx);
                if (rk < need && idx != 0) sm[idx] = 0.f;
            }
        } else if (t == 0) {
            int rk = 0;
            for (int i = 0; i < NN; i++) {
                if (__float_as_uint(sm[i]) == T) {
                    if (rk < need && i != 0) sm[i] = 0.f;
                    rk++;
                }
            }
        }
    }
    __syncthreads();

    // ---- row sums: warp per row ----
    for (int r = wid; r < N197; r += 16) {
        const float* row = sm + r * N197;
        float s = 0.f;
#pragma unroll
        for (int c = lane; c < N197; c += 32) s += row[c];
#pragma unroll
        for (int o = 16; o; o >>= 1) s += __shfl_xor_sync(0xffffffffu, s, o);
        if (lane == 0) rowden[r] = s + 1.0f;   // the *0.5 cancels: (x+d)/(sum+1)
    }
    __syncthreads();

    // ---- normalized float4 write into zero-padded 256x208 buffer ----
    float4* o4 = (float4*)(g_norm + (long)lb * (PADR * PADC));
    const int NV = PADR * PADC / 4;            // 13312
    const int C4 = PADC / 4;                   // 52
    for (int i = t; i < NV; i += NT) {
        int r  = i / C4;
        int c  = (i - r * C4) * 4;
        float4 val = make_float4(0.f, 0.f, 0.f, 0.f);
        if (r < N197) {
            float den = rowden[r];
            float* e = &val.x;
#pragma unroll
            for (int j = 0; j < 4; j++) {
                int cc = c + j;
                if (cc < N197) e[j] = (sm[r * N197 + cc] + (r == cc ? 1.f : 0.f)) / den;
            }
        }
        o4[i] = val;
    }
}

// ---------------------------------------------------------------------------
// 3) out[b] = A11[b] @ A4[b]; padded inputs -> guard-free mainloop
// ---------------------------------------------------------------------------
#define BM 64
#define BN 64
#define BK 16
__global__ void __launch_bounds__(256) gemm_kernel(float* __restrict__ C) {
    const int b = blockIdx.z;
    const float* A = g_norm + (long)(NBATCH + b) * (PADR * PADC);  // layer 11
    const float* B = g_norm + (long)b * (PADR * PADC);             // layer 4
    C += (long)b * NN;

    __shared__ float As[BK][BM];
    __shared__ float Bs[BK][BN + 4];

    const int tid = threadIdx.x;
    const int tx = tid & 15, ty = tid >> 4;
    const int row0 = blockIdx.y * BM, col0 = blockIdx.x * BN;

    float acc[4][4] = {};

    for (int k0 = 0; k0 < PADC; k0 += BK) {
        {   // As: 64 rows x 16 k, transposed; one float4 per thread
            int r = tid >> 2, cq = tid & 3;
            float4 a = *(const float4*)&A[(row0 + r) * PADC + k0 + cq * 4];
            As[cq * 4 + 0][r] = a.x;
            As[cq * 4 + 1][r] = a.y;
            As[cq * 4 + 2][r] = a.z;
            As[cq * 4 + 3][r] = a.w;
        }
        {   // Bs: 16 k x 64 cols; one float4 per thread
            int kr = tid >> 4, cq = tid & 15;
            float4 bv = *(const float4*)&B[(k0 + kr) * PADC + col0 + cq * 4];
            *(float4*)&Bs[kr][cq * 4] = bv;
        }
        __syncthreads();
#pragma unroll
        for (int kk = 0; kk < BK; kk++) {
            float4 av = *(const float4*)&As[kk][ty * 4];
            float4 bv = *(const float4*)&Bs[kk][tx * 4];
            float am[4] = {av.x, av.y, av.z, av.w};
            float bn[4] = {bv.x, bv.y, bv.z, bv.w};
#pragma unroll
            for (int m = 0; m < 4; m++)
#pragma unroll
                for (int n = 0; n < 4; n++) acc[m][n] += am[m] * bn[n];
        }
        __syncthreads();
    }

#pragma unroll
    for (int m = 0; m < 4; m++) {
        int gr = row0 + ty * 4 + m;
        if (gr >= N197) continue;
#pragma unroll
        for (int n = 0; n < 4; n++) {
            int gc = col0 + tx * 4 + n;
            if (gc < N197) C[gr * N197 + gc] = acc[m][n];
        }
    }
}

// ---------------------------------------------------------------------------
extern "C" void kernel_launch(void* const* d_in, const int* in_sizes, int n_in,
                              void* d_out, int out_size) {
    const float* attn = (const float*)d_in[0];  // (12,32,12,197,197) fp32
    float* out = (float*)d_out;                 // (32,197,197) fp32
    (void)in_sizes; (void)n_in; (void)out_size;

    // allow 155,236 B of dynamic smem for the fused kernel (idempotent, capture-safe)
    cudaFuncSetAttribute(fused_kernel, cudaFuncAttributeMaxDynamicSharedMemorySize,
                         NN * (int)sizeof(float));

    dim3 gm(40, NLAY * NBATCH);
    mean_kernel<<<gm, 256>>>(attn);
    fused_kernel<<<NLAY * NBATCH, NT, NN * sizeof(float)>>>();
    dim3 gg((N197 + BN - 1) / BN, (N197 + BM - 1) / BM, NBATCH);
    gemm_kernel<<<gg, 256>>>(out);
}

// round 4
// speedup vs baseline: 2.5331x; 1.4680x over previous
#include <cuda_runtime.h>

#define N197   197
#define NN     38809        // 197*197
#define NNP    38812        // padded stride (float4-aligned)
#define NBATCH 32
#define NLAY   2            // processed layers: 4 and 11
#define KDISC  9702         // int(197*197*0.25)
#define PADR   256
#define PADC   208
#define NTF    1024         // fused kernel threads

__device__ float    g_attn[NLAY * NBATCH * NNP];
__device__ float    g_norm[NLAY * NBATCH * PADR * PADC];
__device__ unsigned g_hist[NLAY * NBATCH * 4096];

// ---------------------------------------------------------------------------
// 0) zero the global round-0 histograms (graph-safe, deterministic)
// ---------------------------------------------------------------------------
__global__ void zero_hist() {
    for (int i = threadIdx.x; i < 4096; i += blockDim.x)
        g_hist[blockIdx.x * 4096 + i] = 0u;
}

// ---------------------------------------------------------------------------
// 1) mean over heads + round-0 histogram (top 12 float bits), hidden under DRAM
// ---------------------------------------------------------------------------
__global__ void __launch_bounds__(256) mean_kernel(const float* __restrict__ in) {
    __shared__ unsigned hist[4096];
    for (int i = threadIdx.x; i < 4096; i += 256) hist[i] = 0u;
    __syncthreads();

    int lb = blockIdx.y;                 // 0..63 = li*32 + b
    int li = lb >> 5, b = lb & 31;
    int layer = li ? 11 : 4;
    const float* __restrict__ base = in + ((long)(layer * NBATCH + b) * 12) * NN;
    float* dst = g_attn + (long)lb * NNP;
    const int lane   = threadIdx.x & 31;
    const int stride = gridDim.x * 256;
    const int ITER   = (NN + stride - 1) / stride;

    for (int k = 0; k < ITER; k++) {
        int p = k * stride + blockIdx.x * 256 + threadIdx.x;
        bool valid = p < NN;
        float s = 0.f;
        if (valid) {
#pragma unroll
            for (int h = 0; h < 12; h++) s += __ldg(&base[(long)h * NN + p]);
            s *= (1.0f / 12.0f);
            dst[p] = s;
        }
        unsigned key = __float_as_uint(s) >> 20;
        unsigned m = __ballot_sync(0xffffffffu, valid);
        if (valid) {
            unsigned grp = __match_any_sync(m, key);
            if (lane == (int)__ffs(grp) - 1) atomicAdd(&hist[key], __popc(grp));
        }
    }
    __syncthreads();
    for (int i = threadIdx.x; i < 4096; i += 256) {
        unsigned c = hist[i];
        if (c) atomicAdd(&g_hist[lb * 4096 + i], c);
    }
}

// ---------------------------------------------------------------------------
// block-wide "pick the bucket containing rank" over nb counters
// results via s_out: [0]=chosen bucket, [1]=rank within bucket, [2]=count below
// ---------------------------------------------------------------------------
template<int PER>
__device__ __forceinline__ void block_pick(const unsigned* cnts, int nb, int rank,
                                           unsigned* wtot, int* s_out) {
    const int t = threadIdx.x, lane = t & 31, wid = t >> 5;
    const int base = t * PER;
    unsigned h[PER];
    unsigned sum = 0;
    if (base < nb) {
#pragma unroll
        for (int j = 0; j < PER; j++) { h[j] = cnts[base + j]; sum += h[j]; }
    }
    unsigned x = sum;
#pragma unroll
    for (int o = 1; o < 32; o <<= 1) {
        unsigned y = __shfl_up_sync(0xffffffffu, x, o);
        if (lane >= o) x += y;
    }
    if (lane == 31) wtot[wid] = x;
    __syncthreads();
    if (wid == 0) {
        unsigned y = wtot[lane];
#pragma unroll
        for (int o = 1; o < 32; o <<= 1) {
            unsigned z = __shfl_up_sync(0xffffffffu, y, o);
            if (lane >= o) y += z;
        }
        wtot[lane] = y;
    }
    __syncthreads();
    unsigned excl = x - sum + (wid ? wtot[wid - 1] : 0u);
    if (base < nb && (unsigned)rank >= excl && (unsigned)rank < excl + sum) {
        unsigned c = excl; int ch = base;
#pragma unroll
        for (int j = 0; j < PER; j++) {
            if (c + h[j] > (unsigned)rank) { ch = base + j; break; }
            c += h[j];
        }
        s_out[0] = ch; s_out[1] = rank - (int)c; s_out[2] = (int)c;
    }
    __syncthreads();
}

// ---------------------------------------------------------------------------
// 2) fused: load->smem (+round-1 hist) -> pick -> [rare round-2 / tie pass]
//    -> discard+rowsum -> normalized padded write
// ---------------------------------------------------------------------------
__global__ void __launch_bounds__(NTF) fused_kernel() {
    extern __shared__ float sm[];          // NN floats
    __shared__ unsigned hist[4096];
    __shared__ unsigned wtot[32];
    __shared__ int s_pick[3];
    __shared__ float rowden[N197];

    const int lb = blockIdx.x;
    const int t = threadIdx.x, lane = t & 31, wid = t >> 5;

    // ---- round 0: pick top-12 bucket from the global histogram ----
    block_pick<4>(&g_hist[lb * 4096], 4096, KDISC - 1, wtot, s_pick);
    const int B1 = s_pick[0];
    int rank = s_pick[1];

    for (int i = t; i < 4096; i += NTF) hist[i] = 0u;
    __syncthreads();

    // ---- load matrix to smem + round-1 hist (bits 19..8 of matching keys) ----
    const float* src = g_attn + (long)lb * NNP;
    const float4* s4 = (const float4*)src;
    float4* d4 = (float4*)sm;
    const int N4 = NN / 4;                 // 9702
    const int IT4 = (N4 + NTF - 1) / NTF;  // 10
    for (int k = 0; k < IT4; k++) {
        int i = k * NTF + t;
        bool valid = i < N4;
        float4 a = valid ? s4[i] : make_float4(0.f, 0.f, 0.f, 0.f);
        if (valid) d4[i] = a;
        const float vv[4] = {a.x, a.y, a.z, a.w};
#pragma unroll
        for (int j = 0; j < 4; j++) {
            unsigned key = __float_as_uint(vv[j]);
            bool ok = valid && (int)(key >> 20) == B1;
            unsigned m = __ballot_sync(0xffffffffu, ok);
            if (ok) {
                unsigned bkt = (key >> 8) & 0xFFFu;
                unsigned grp = __match_any_sync(m, bkt);
                if (lane == (int)__ffs(grp) - 1) atomicAdd(&hist[bkt], __popc(grp));
            }
        }
    }
    if (t == 0) {                          // tail element 38808
        float v = src[NN - 1]; sm[NN - 1] = v;
        unsigned key = __float_as_uint(v);
        if ((int)(key >> 20) == B1) atomicAdd(&hist[(key >> 8) & 0xFFFu], 1u);
    }
    __syncthreads();

    block_pick<4>(hist, 4096, rank, wtot, s_pick);
    const int B2 = s_pick[0];
    rank = s_pick[1];
    const unsigned K24 = ((unsigned)B1 << 12) | (unsigned)B2;
    const unsigned ties2 = hist[B2];

    int mode;           // 0: zero key24<=K24 | 1: zero key<=T | 2: zero key<T (ties pre-zeroed)
    unsigned T = 0;
    if (ties2 == 1u) {
        mode = 0;       // the kth element is the unique key24==K24 element
    } else {
        // ---- round 2: low 8 bits among key24==K24 ----
        for (int i = t; i < 256; i += NTF) hist[i] = 0u;
        __syncthreads();
        const int IT = (NN + NTF - 1) / NTF;   // 38
        for (int k = 0; k < IT; k++) {
            int i = k * NTF + t;
            unsigned key = (i < NN) ? __float_as_uint(sm[i]) : 0u;
            bool ok = (i < NN) && (key >> 8) == K24;
            unsigned m = __ballot_sync(0xffffffffu, ok);
            if (ok) {
                unsigned bkt = key & 0xFFu;
                unsigned grp = __match_any_sync(m, bkt);
                if (lane == (int)__ffs(grp) - 1) atomicAdd(&hist[bkt], __popc(grp));
            }
        }
        __syncthreads();
        block_pick<1>(hist, 256, rank, wtot, s_pick);
        const int B3 = s_pick[0];
        const int rank3 = s_pick[1];
        T = (K24 << 8) | (unsigned)B3;
        const unsigned ties3 = hist[B3];
        const int need = rank3 + 1;            // #(==T) among the k smallest
        if ((unsigned)need == ties3) {
            mode = 1;
        } else {
            mode = 2;
            // index-ordered tie zeroing: contiguous segments + block scan
            const int SEG = (NN + NTF - 1) / NTF;   // 38
            int start = t * SEG, end = min(start + SEG, NN);
            int cnt = 0;
            for (int i = start; i < end; i++)
                if (__float_as_uint(sm[i]) == T) cnt++;
            int x = cnt;
#pragma unroll
            for (int o = 1; o < 32; o <<= 1) {
                int y = __shfl_up_sync(0xffffffffu, x, o);
                if (lane >= o) x += y;
            }
            if (lane == 31) wtot[wid] = (unsigned)x;
            __syncthreads();
            if (wid == 0) {
                unsigned y = wtot[lane];
#pragma unroll
                for (int o = 1; o < 32; o <<= 1) {
                    unsigned z = __shfl_up_sync(0xffffffffu, y, o);
                    if (lane >= o) y += z;
                }
                wtot[lane] = y;
            }
            __syncthreads();
            int pre = x - cnt + (wid ? (int)wtot[wid - 1] : 0);
            for (int i = start; i < end; i++) {
                if (__float_as_uint(sm[i]) == T) {
                    if (pre < need && i != 0) sm[i] = 0.f;
                    pre++;
                }
            }
            __syncthreads();
        }
    }

    // ---- discard + row sums in one pass (warp per row) ----
    for (int r = wid; r < N197; r += 32) {
        float s = 0.f;
        const int rowbase = r * N197;
        for (int c = lane; c < N197; c += 32) {
            int i = rowbase + c;
            float v = sm[i];
            unsigned key = __float_as_uint(v);
            bool z = (mode == 0) ? ((key >> 8) <= K24)
                   : (mode == 1) ? (key <= T)
                                 : (key < T);
            if (z && i != 0) { sm[i] = 0.f; v = 0.f; }
            s += v;
        }
#pragma unroll
        for (int o = 16; o; o >>= 1) s += __shfl_xor_sync(0xffffffffu, s, o);
        if (lane == 0) rowden[r] = s + 1.0f;    // the *0.5 cancels: (x+d)/(sum+1)
    }
    __syncthreads();

    // ---- normalized float4 write into zero-padded 256x208 buffer ----
    float4* o4 = (float4*)(g_norm + (long)lb * (PADR * PADC));
    const int NV = PADR * PADC / 4;            // 13312
    const int C4 = PADC / 4;                   // 52
    for (int i = t; i < NV; i += NTF) {
        int r = i / C4;
        int c = (i - r * C4) * 4;
        float4 val = make_float4(0.f, 0.f, 0.f, 0.f);
        if (r < N197) {
            float inv = 1.0f / rowden[r];
            float* e = &val.x;
#pragma unroll
            for (int j = 0; j < 4; j++) {
                int cc = c + j;
                if (cc < N197) e[j] = (sm[r * N197 + cc] + (r == cc ? 1.f : 0.f)) * inv;
            }
        }
        o4[i] = val;
    }
}

// ---------------------------------------------------------------------------
// 3) out[b] = A11[b] @ A4[b]; padded inputs -> guard-free mainloop
// ---------------------------------------------------------------------------
#define BM 64
#define BN 64
#define BK 16
__global__ void __launch_bounds__(256) gemm_kernel(float* __restrict__ C) {
    const int b = blockIdx.z;
    const float* A = g_norm + (long)(NBATCH + b) * (PADR * PADC);  // layer 11
    const float* B = g_norm + (long)b * (PADR * PADC);             // layer 4
    C += (long)b * NN;

    __shared__ float As[BK][BM];
    __shared__ float Bs[BK][BN + 4];

    const int tid = threadIdx.x;
    const int tx = tid & 15, ty = tid >> 4;
    const int row0 = blockIdx.y * BM, col0 = blockIdx.x * BN;

    float acc[4][4] = {};

    for (int k0 = 0; k0 < PADC; k0 += BK) {
        {
            int r = tid >> 2, cq = tid & 3;
            float4 a = *(const float4*)&A[(row0 + r) * PADC + k0 + cq * 4];
            As[cq * 4 + 0][r] = a.x;
            As[cq * 4 + 1][r] = a.y;
            As[cq * 4 + 2][r] = a.z;
            As[cq * 4 + 3][r] = a.w;
        }
        {
            int kr = tid >> 4, cq = tid & 15;
            float4 bv = *(const float4*)&B[(k0 + kr) * PADC + col0 + cq * 4];
            *(float4*)&Bs[kr][cq * 4] = bv;
        }
        __syncthreads();
#pragma unroll
        for (int kk = 0; kk < BK; kk++) {
            float4 av = *(const float4*)&As[kk][ty * 4];
            float4 bv = *(const float4*)&Bs[kk][tx * 4];
            float am[4] = {av.x, av.y, av.z, av.w};
            float bn[4] = {bv.x, bv.y, bv.z, bv.w};
#pragma unroll
            for (int m = 0; m < 4; m++)
#pragma unroll
                for (int n = 0; n < 4; n++) acc[m][n] += am[m] * bn[n];
        }
        __syncthreads();
    }

#pragma unroll
    for (int m = 0; m < 4; m++) {
        int gr = row0 + ty * 4 + m;
        if (gr >= N197) continue;
#pragma unroll
        for (int n = 0; n < 4; n++) {
            int gc = col0 + tx * 4 + n;
            if (gc < N197) C[gr * N197 + gc] = acc[m][n];
        }
    }
}

// ---------------------------------------------------------------------------
extern "C" void kernel_launch(void* const* d_in, const int* in_sizes, int n_in,
                              void* d_out, int out_size) {
    const float* attn = (const float*)d_in[0];  // (12,32,12,197,197) fp32
    float* out = (float*)d_out;                 // (32,197,197) fp32
    (void)in_sizes; (void)n_in; (void)out_size;

    cudaFuncSetAttribute(fused_kernel, cudaFuncAttributeMaxDynamicSharedMemorySize,
                         NN * (int)sizeof(float));

    zero_hist<<<NLAY * NBATCH, 256>>>();
    dim3 gm(40, NLAY * NBATCH);
    mean_kernel<<<gm, 256>>>(attn);
    fused_kernel<<<NLAY * NBATCH, NTF, NN * sizeof(float)>>>();
    dim3 gg((N197 + BN - 1) / BN, (N197 + BM - 1) / BM, NBATCH);
    gemm_kernel<<<gg, 256>>>(out);
}